// round 14
// baseline (speedup 1.0000x reference)
#include <cuda_runtime.h>
#include <cstdint>
#include <math.h>

// Round 13: R12 pipeline + P5 split across teams (producer does nb 0-1 after
// P4; consumer does nb 2-3) + sSC double-buffered by qb parity; consumer BEQ
// arrive moved after P6 to guard sSC reuse.

#define NT 384
#define GRID 148

typedef unsigned long long ull;

// shared memory float offsets
#define OFF_WKT   0        // [128][65]
#define OFF_WV    8320     // [64][128]
#define OFF_WO    16512    // [128][64]
#define OFF_BQ    24704
#define OFF_BV    24832
#define OFF_BO    24960
#define OFF_N     25024    // [3][4][20][68] = 16320
#define OFF_V     41344    // [3][4][20] = 240
#define OFF_QK    41584    // [2][4][8][72] = 4608
#define OFF_RAW   46192    // [192][4] = 768
#define OFF_Q     46960    // [128][4] = 512
#define OFF_PART  47472    // [4][128][2] ull = 2048 floats
#define OFF_SC    49520    // [2][4][8][28] = 1792 (qb-parity double buffer)
#define OFF_M     51312    // [2][4][8][72] = 4608 (parity-buffered)
#define OFF_CTX   55920    // [8][128] = 1024
#define OFF_RED8  56944    // [2][8][64] = 1024
#define SMEM_FLOATS 57968
#define SMEM_BYTES  (SMEM_FLOATS * 4)   // 231872 B (cap 232448)

// named barrier ids
#define BFULL0 1
#define BEQ0   3
#define BEN0   5
#define BPROD  8
#define BCONS  9

#define BAR_SYNC(id, cnt)   asm volatile("bar.sync %0, %1;"   :: "r"(id), "r"(cnt) : "memory")
#define BAR_ARRIVE(id, cnt) asm volatile("bar.arrive %0, %1;" :: "r"(id), "r"(cnt) : "memory")
#define CP_COMMIT()         asm volatile("cp.async.commit_group;" ::: "memory")
#define CP_WAIT1()          asm volatile("cp.async.wait_group 1;" ::: "memory")

__device__ __forceinline__ ull pk1(float a) {
    ull r; asm("mov.b64 %0, {%1,%1};" : "=l"(r) : "f"(a)); return r;
}
__device__ __forceinline__ ull pk2(float a, float b) {
    ull r; asm("mov.b64 %0, {%1,%2};" : "=l"(r) : "f"(a), "f"(b)); return r;
}
__device__ __forceinline__ void fma2(ull& d, ull a, ull b) {
    asm("fma.rn.f32x2 %0, %1, %2, %0;" : "+l"(d) : "l"(a), "l"(b));
}
__device__ __forceinline__ ull add2(ull a, ull b) {
    ull r; asm("add.rn.f32x2 %0, %1, %2;" : "=l"(r) : "l"(a), "l"(b)); return r;
}
__device__ __forceinline__ ull mul2(ull a, ull b) {
    ull r; asm("mul.rn.f32x2 %0, %1, %2;" : "=l"(r) : "l"(a), "l"(b)); return r;
}
__device__ __forceinline__ float2 upk(ull a) {
    float2 f; asm("mov.b64 {%0,%1}, %2;" : "=f"(f.x), "=f"(f.y) : "l"(a)); return f;
}

__device__ __forceinline__ void issue_node_cp(unsigned int sbase, const float* ne,
                                              int b0, int nbuf, int t) {
    const float4* src = reinterpret_cast<const float4*>(ne) + (size_t)b0 * 320;
    #pragma unroll
    for (int kk = 0; kk < 5; ++kk) {
        int g   = t + kk * 256;
        int nb  = g / 320;
        int rem = g - nb * 320;
        unsigned int dstf = (unsigned int)(OFF_N + nbuf * 5440 + nb * 1360 +
                                           ((rem >> 4) * 17 + (rem & 15)) * 4);
        asm volatile("cp.async.ca.shared.global [%0], [%1], 16;"
                     :: "r"(sbase + dstf * 4), "l"(src + g) : "memory");
    }
}

__global__ void __launch_bounds__(NT, 1)
mha_state_encoder_kernel(const float* __restrict__ node_embed,
                         const int*   __restrict__ start_idx,
                         const int*   __restrict__ end_idx,
                         const int*   __restrict__ pad_idx,
                         const float* __restrict__ Wq, const float* __restrict__ bq,
                         const float* __restrict__ Wk,
                         const float* __restrict__ Wv, const float* __restrict__ bv,
                         const float* __restrict__ Wo, const float* __restrict__ bo,
                         float* __restrict__ out, int B)
{
    extern __shared__ float sm[];
    float* sWKT = sm + OFF_WKT;
    float* sWV  = sm + OFF_WV;
    float* sWO  = sm + OFF_WO;
    float* sBQ  = sm + OFF_BQ;
    float* sBV  = sm + OFF_BV;
    float* sBO  = sm + OFF_BO;
    float* sN   = sm + OFF_N;
    float* sV   = sm + OFF_V;
    float* sQK  = sm + OFF_QK;
    float* sRAW = sm + OFF_RAW;
    float* sSC  = sm + OFF_SC;
    float* sM   = sm + OFF_M;
    float* sCTX = sm + OFF_CTX;
    float* sRED8= sm + OFF_RED8;
    ull*   sQ2  = reinterpret_cast<ull*>(sm + OFF_Q);
    ull*   sPT  = reinterpret_cast<ull*>(sm + OFF_PART);

    unsigned int sbase;
    asm("{ .reg .u64 tt; cvta.to.shared.u64 tt, %1; cvt.u32.u64 %0, tt; }"
        : "=r"(sbase) : "l"(sm));

    const int t  = threadIdx.x;
    const int Qn = B >> 2;
    const int q0 = blockIdx.x;

    // ---- stage weights (whole CTA) ----
    for (int i = t; i < 8192; i += NT) {
        int d = i >> 7, c = i & 127;
        sWKT[c * 65 + d] = Wk[i];
    }
    for (int i = t; i < 2048; i += NT) {
        reinterpret_cast<float4*>(sWV)[i] = reinterpret_cast<const float4*>(Wv)[i];
        reinterpret_cast<float4*>(sWO)[i] = reinterpret_cast<const float4*>(Wo)[i];
    }
    if (t < 128) { sBQ[t] = bq[t]; sBV[t] = bv[t]; }
    if (t < 64)  sBO[t] = bo[t];
    __syncthreads();

    if (t < 256) {
        // ======================= PRODUCER (256 threads) =======================
        const int cl = t & 63;
        const int rg = t >> 6;
        float wq[96];
        {
            const float* src = Wq + (size_t)(rg * 48) * 128 + cl;
            #pragma unroll
            for (int i = 0; i < 24; ++i) {
                wq[4*i+0] = src[(size_t)(2*i)   * 128];
                wq[4*i+1] = src[(size_t)(2*i)   * 128 + 64];
                wq[4*i+2] = src[(size_t)(2*i+1) * 128];
                wq[4*i+3] = src[(size_t)(2*i+1) * 128 + 64];
            }
        }
        const int gg  = t - 128;
        const int gnb = gg & 3;
        const int gwh = (gg >> 2) & 1;
        const int gdq = gg >> 3;

        float4 pfG = make_float4(0.f, 0.f, 0.f, 0.f);
        int pfP = 0, gi_next = 0;

        if (q0 < Qn)        issue_node_cp(sbase, node_embed, q0 * 4, 0, t);
        CP_COMMIT();
        if (q0 + GRID < Qn) issue_node_cp(sbase, node_embed, (q0 + GRID) * 4, 1, t);
        CP_COMMIT();
        if (q0 < Qn) {
            if (t >= 128) {
                int gi = gwh ? end_idx[q0 * 4 + gnb] : start_idx[q0 * 4 + gnb];
                pfG = *reinterpret_cast<const float4*>(node_embed + (size_t)gi * 64 + gdq * 4);
                int qn = q0 + GRID;
                if (qn < Qn) gi_next = gwh ? end_idx[qn * 4 + gnb] : start_idx[qn * 4 + gnb];
            }
            if (t < 80) pfP = pad_idx[q0 * 80 + t];
        }

        int it = 0, nb3 = 0;
        for (int q = q0; q < Qn; q += GRID, ++it) {
            const int qb = it & 1;

            CP_WAIT1();

            if (t >= 128) {
                int r0 = 64 + gwh * 64 + gdq * 4;
                sRAW[(r0 + 0) * 4 + gnb] = pfG.x;
                sRAW[(r0 + 1) * 4 + gnb] = pfG.y;
                sRAW[(r0 + 2) * 4 + gnb] = pfG.z;
                sRAW[(r0 + 3) * 4 + gnb] = pfG.w;
            }
            if (t < 80) sV[nb3 * 80 + t] = (pfP >= 0) ? 1.0f : 0.0f;
            if (q + GRID < Qn) {
                if (t >= 128) {
                    pfG = *reinterpret_cast<const float4*>(node_embed + (size_t)gi_next * 64 + gdq * 4);
                    int qn2 = q + 2 * GRID;
                    if (qn2 < Qn) gi_next = gwh ? end_idx[qn2 * 4 + gnb] : start_idx[qn2 * 4 + gnb];
                }
                if (t < 80) pfP = pad_idx[(q + GRID) * 80 + t];
            }
            BAR_SYNC(BPROD, 256);

            // ---- P2: agg (column sums, f32x2) ----
            if (t < 64) {
                int nb = t >> 4, dq = t & 15;
                const ulonglong2* col = reinterpret_cast<const ulonglong2*>(sN + nb3 * 5440 + nb * 1360) + dq;
                ull s01 = 0, s23 = 0;
                #pragma unroll
                for (int j = 0; j < 20; ++j) {
                    ulonglong2 x = col[j * 17];
                    s01 = add2(s01, x.x);
                    s23 = add2(s23, x.y);
                }
                float2 a01 = upk(s01), a23 = upk(s23);
                int r0 = dq * 4;
                sRAW[(r0 + 0) * 4 + nb] = a01.x;
                sRAW[(r0 + 1) * 4 + nb] = a01.y;
                sRAW[(r0 + 2) * 4 + nb] = a23.x;
                sRAW[(r0 + 3) * 4 + nb] = a23.y;
            }
            BAR_SYNC(BPROD, 256);

            // ---- P3a: q partials ----
            {
                const ulonglong2* pR = reinterpret_cast<const ulonglong2*>(sRAW) + rg * 48;
                ull a0 = 0, a1 = 0, b0u = 0, b1u = 0;
                #pragma unroll
                for (int i = 0; i < 24; ++i) {
                    ulonglong2 x = pR[2 * i];
                    ulonglong2 y = pR[2 * i + 1];
                    ull w0 = pk1(wq[4*i+0]), w1 = pk1(wq[4*i+1]);
                    ull w2 = pk1(wq[4*i+2]), w3 = pk1(wq[4*i+3]);
                    fma2(a0,  w0, x.x); fma2(a1,  w0, x.y);
                    fma2(b0u, w1, x.x); fma2(b1u, w1, x.y);
                    fma2(a0,  w2, y.x); fma2(a1,  w2, y.y);
                    fma2(b0u, w3, y.x); fma2(b1u, w3, y.y);
                }
                ull* dA = sPT + rg * 256 + cl * 2;
                dA[0] = a0; dA[1] = a1;
                ull* dB = sPT + rg * 256 + (cl + 64) * 2;
                dB[0] = b0u; dB[1] = b1u;
            }
            BAR_SYNC(BPROD, 256);

            // ---- P3b: combine + bias + 0.25 ----
            {
                int c = t >> 1, pp = t & 1;
                int o = c * 2 + pp;
                ull v = add2(add2(sPT[o], sPT[256 + o]),
                             add2(sPT[512 + o], sPT[768 + o]));
                v = add2(v, pk1(sBQ[c]));
                v = mul2(v, pk1(0.25f));
                sQ2[c * 2 + pp] = v;
            }
            BAR_SYNC(BPROD, 256);

            // ---- P4: qk -> sQK[qb] (also gates sSC[qb] reuse) ----
            if (it >= 2) BAR_SYNC(BEQ0 + qb, 384);
            #pragma unroll
            for (int p = 0; p < 2; ++p) {
                int v2 = t + p * 256;
                int h = v2 >> 6, d = v2 & 63;
                const float* wkb = sWKT + h * 16 * 65 + d;
                const ulonglong2* q2 = reinterpret_cast<const ulonglong2*>(sQ2) + h * 16;
                ull a01 = 0, a23 = 0;
                #pragma unroll
                for (int i = 0; i < 16; ++i) {
                    ull wp = pk1(wkb[i * 65]);
                    ulonglong2 qv = q2[i];
                    fma2(a01, wp, qv.x);
                    fma2(a23, wp, qv.y);
                }
                float2 f01 = upk(a01), f23 = upk(a23);
                float* dst = sQK + qb * 2304 + h * 72 + d;
                dst[0 * 576] = f01.x; dst[1 * 576] = f01.y;
                dst[2 * 576] = f23.x; dst[3 * 576] = f23.y;
            }
            BAR_SYNC(BPROD, 256);   // qk visible to producer P5a threads

            // ---- P5a: producer computes scores for nb 0..1 -> sSC[qb] ----
            if (t < 40) {
                int nb = t / 20, j = t - nb * 20;
                const ulonglong2* n2 = reinterpret_cast<const ulonglong2*>(
                    sN + nb3 * 5440 + nb * 1360 + j * 68);
                const float* qkb = sQK + qb * 2304 + nb * 576;
                float rsum;
                {
                    ull rs = 0;
                    #pragma unroll
                    for (int k = 0; k < 16; ++k) {
                        ulonglong2 x = n2[k];
                        rs = add2(rs, add2(x.x, x.y));
                    }
                    float2 rf = upk(rs);
                    rsum = rf.x + rf.y;
                }
                float msk = (sV[nb3 * 80 + nb * 20 + j] == 0.f || rsum == 0.f) ? -1e9f : 0.f;
                #pragma unroll
                for (int hh = 0; hh < 2; ++hh) {
                    const float* qh = qkb + (hh * 4) * 72;
                    ull a0 = 0, a1 = 0, a2 = 0, a3 = 0;
                    #pragma unroll
                    for (int k = 0; k < 16; ++k) {
                        ulonglong2 x = n2[k];
                        ulonglong2 q0v = *reinterpret_cast<const ulonglong2*>(qh + 0 * 72 + k * 4);
                        ulonglong2 q1v = *reinterpret_cast<const ulonglong2*>(qh + 1 * 72 + k * 4);
                        ulonglong2 q2v = *reinterpret_cast<const ulonglong2*>(qh + 2 * 72 + k * 4);
                        ulonglong2 q3v = *reinterpret_cast<const ulonglong2*>(qh + 3 * 72 + k * 4);
                        fma2(a0, q0v.x, x.x); fma2(a0, q0v.y, x.y);
                        fma2(a1, q1v.x, x.x); fma2(a1, q1v.y, x.y);
                        fma2(a2, q2v.x, x.x); fma2(a2, q2v.y, x.y);
                        fma2(a3, q3v.x, x.x); fma2(a3, q3v.y, x.y);
                    }
                    float* dst = sSC + qb * 896 + nb * 224 + (hh * 4) * 28 + j;
                    float2 f;
                    f = upk(a0); dst[0 * 28] = f.x + f.y + msk;
                    f = upk(a1); dst[1 * 28] = f.x + f.y + msk;
                    f = upk(a2); dst[2 * 28] = f.x + f.y + msk;
                    f = upk(a3); dst[3 * 28] = f.x + f.y + msk;
                }
            }
            BAR_ARRIVE(BFULL0 + qb, 384);

            // ---- issue node cp.async for group q+2*GRID ----
            {
                int nb3p2 = nb3 + 2; if (nb3p2 >= 3) nb3p2 -= 3;
                if (q + 2 * GRID < Qn) {
                    if (it >= 1) BAR_SYNC(BEN0 + nb3p2, 384);
                    issue_node_cp(sbase, node_embed, (q + 2 * GRID) * 4, nb3p2, t);
                }
                CP_COMMIT();
            }
            if (++nb3 == 3) nb3 = 0;
        }
    } else {
        // ======================= CONSUMER (128 threads) =======================
        const int u = t - 256;
        int it = 0, nb3 = 0;
        int b0_prev = 0;
        for (int q = q0; q < Qn; q += GRID, ++it) {
            const int b0 = q * 4;
            const int qb  = it & 1;
            const int par = it & 1;
            const float* nbase = sN + nb3 * 5440;
            const float* vbase = sV + nb3 * 80;
            const float* qkB   = sQK + qb * 2304;
            float* sSCb = sSC + qb * 896;
            float* sMp  = sM + par * 2304;

            BAR_SYNC(BFULL0 + qb, 384);   // qk + nodes + valid + scores(nb0-1) ready

            // ---- P5b: scores for nb 2..3 only ----
            if (u < 40) {
                int nb = 2 + u / 20, j = u % 20;
                const ulonglong2* n2 = reinterpret_cast<const ulonglong2*>(nbase + nb * 1360 + j * 68);
                const float* qkb = qkB + nb * 576;
                ull acc0 = 0, acc1 = 0, acc2 = 0, acc3 = 0;
                ull acc4 = 0, acc5 = 0, acc6 = 0, acc7 = 0;
                ull rs = 0;
                #pragma unroll
                for (int k = 0; k < 16; ++k) {
                    ulonglong2 x = n2[k];
                    rs = add2(rs, add2(x.x, x.y));
                    ulonglong2 q0v = *reinterpret_cast<const ulonglong2*>(qkb + 0 * 72 + k * 4);
                    ulonglong2 q1v = *reinterpret_cast<const ulonglong2*>(qkb + 1 * 72 + k * 4);
                    ulonglong2 q2v = *reinterpret_cast<const ulonglong2*>(qkb + 2 * 72 + k * 4);
                    ulonglong2 q3v = *reinterpret_cast<const ulonglong2*>(qkb + 3 * 72 + k * 4);
                    ulonglong2 q4v = *reinterpret_cast<const ulonglong2*>(qkb + 4 * 72 + k * 4);
                    ulonglong2 q5v = *reinterpret_cast<const ulonglong2*>(qkb + 5 * 72 + k * 4);
                    ulonglong2 q6v = *reinterpret_cast<const ulonglong2*>(qkb + 6 * 72 + k * 4);
                    ulonglong2 q7v = *reinterpret_cast<const ulonglong2*>(qkb + 7 * 72 + k * 4);
                    fma2(acc0, q0v.x, x.x); fma2(acc0, q0v.y, x.y);
                    fma2(acc1, q1v.x, x.x); fma2(acc1, q1v.y, x.y);
                    fma2(acc2, q2v.x, x.x); fma2(acc2, q2v.y, x.y);
                    fma2(acc3, q3v.x, x.x); fma2(acc3, q3v.y, x.y);
                    fma2(acc4, q4v.x, x.x); fma2(acc4, q4v.y, x.y);
                    fma2(acc5, q5v.x, x.x); fma2(acc5, q5v.y, x.y);
                    fma2(acc6, q6v.x, x.x); fma2(acc6, q6v.y, x.y);
                    fma2(acc7, q7v.x, x.x); fma2(acc7, q7v.y, x.y);
                }
                float2 rf = upk(rs);
                float rsum = rf.x + rf.y;
                float msk = (vbase[nb * 20 + j] == 0.f || rsum == 0.f) ? -1e9f : 0.f;
                float* dst = sSCb + nb * 224 + j;
                float2 f;
                f = upk(acc0); dst[0 * 28] = f.x + f.y + msk;
                f = upk(acc1); dst[1 * 28] = f.x + f.y + msk;
                f = upk(acc2); dst[2 * 28] = f.x + f.y + msk;
                f = upk(acc3); dst[3 * 28] = f.x + f.y + msk;
                f = upk(acc4); dst[4 * 28] = f.x + f.y + msk;
                f = upk(acc5); dst[5 * 28] = f.x + f.y + msk;
                f = upk(acc6); dst[6 * 28] = f.x + f.y + msk;
                f = upk(acc7); dst[7 * 28] = f.x + f.y + msk;
            }
            BAR_SYNC(BCONS, 128);

            // ---- softmax: 32 rows x 4 lanes ----
            {
                int row = u >> 2, j0 = u & 3;
                int nb = row >> 3, h = row & 7;
                float* base = sSCb + nb * 224 + h * 28;
                const float* vd = vbase + nb * 20;
                float x0 = base[j0], x1 = base[j0+4], x2 = base[j0+8], x3 = base[j0+12], x4 = base[j0+16];
                float mx = fmaxf(fmaxf(fmaxf(x0, x1), fmaxf(x2, x3)), x4);
                mx = fmaxf(mx, __shfl_xor_sync(0xffffffffu, mx, 1));
                mx = fmaxf(mx, __shfl_xor_sync(0xffffffffu, mx, 2));
                float e0 = __expf(x0 - mx), e1 = __expf(x1 - mx), e2 = __expf(x2 - mx);
                float e3 = __expf(x3 - mx), e4 = __expf(x4 - mx);
                float s = ((e0 + e1) + (e2 + e3)) + e4;
                s += __shfl_xor_sync(0xffffffffu, s, 1);
                s += __shfl_xor_sync(0xffffffffu, s, 2);
                float inv = __fdividef(1.f, s);
                base[j0]      = e0 * inv * vd[j0];
                base[j0 + 4]  = e1 * inv * vd[j0 + 4];
                base[j0 + 8]  = e2 * inv * vd[j0 + 8];
                base[j0 + 12] = e3 * inv * vd[j0 + 12];
                base[j0 + 16] = e4 * inv * vd[j0 + 16];
            }
            BAR_SYNC(BCONS, 128);

            // ---- P6: m (4 heads/thread, f32x2) -> sM[par] ----
            {
                int nb = u >> 5, dq = (u >> 1) & 15, hg = u & 1;
                const ulonglong2* n2 = reinterpret_cast<const ulonglong2*>(nbase + nb * 1360) + dq;
                const float* a0 = sSCb + nb * 224 + (hg * 4 + 0) * 28;
                const float* a1 = sSCb + nb * 224 + (hg * 4 + 1) * 28;
                const float* a2 = sSCb + nb * 224 + (hg * 4 + 2) * 28;
                const float* a3 = sSCb + nb * 224 + (hg * 4 + 3) * 28;
                ull m0a = 0, m0b = 0, m1a = 0, m1b = 0;
                ull m2a = 0, m2b = 0, m3a = 0, m3b = 0;
                #pragma unroll
                for (int jq = 0; jq < 5; ++jq) {
                    float4 w0 = *reinterpret_cast<const float4*>(a0 + jq * 4);
                    float4 w1 = *reinterpret_cast<const float4*>(a1 + jq * 4);
                    float4 w2 = *reinterpret_cast<const float4*>(a2 + jq * 4);
                    float4 w3 = *reinterpret_cast<const float4*>(a3 + jq * 4);
                    #pragma unroll
                    for (int jj = 0; jj < 4; ++jj) {
                        ulonglong2 x = n2[(jq * 4 + jj) * 17];
                        float c0 = jj == 0 ? w0.x : jj == 1 ? w0.y : jj == 2 ? w0.z : w0.w;
                        float c1 = jj == 0 ? w1.x : jj == 1 ? w1.y : jj == 2 ? w1.z : w1.w;
                        float c2 = jj == 0 ? w2.x : jj == 1 ? w2.y : jj == 2 ? w2.z : w2.w;
                        float c3 = jj == 0 ? w3.x : jj == 1 ? w3.y : jj == 2 ? w3.z : w3.w;
                        ull p0 = pk1(c0), p1 = pk1(c1), p2 = pk1(c2), p3 = pk1(c3);
                        fma2(m0a, p0, x.x); fma2(m0b, p0, x.y);
                        fma2(m1a, p1, x.x); fma2(m1b, p1, x.y);
                        fma2(m2a, p2, x.x); fma2(m2b, p2, x.y);
                        fma2(m3a, p3, x.x); fma2(m3b, p3, x.y);
                    }
                }
                float* mb = sMp + nb * 576 + (hg * 4) * 72 + dq * 4;
                ulonglong2* mb2;
                mb2 = reinterpret_cast<ulonglong2*>(mb + 0 * 72); mb2->x = m0a; mb2->y = m0b;
                mb2 = reinterpret_cast<ulonglong2*>(mb + 1 * 72); mb2->x = m1a; mb2->y = m1b;
                mb2 = reinterpret_cast<ulonglong2*>(mb + 2 * 72); mb2->x = m2a; mb2->y = m2b;
                mb2 = reinterpret_cast<ulonglong2*>(mb + 3 * 72); mb2->x = m3a; mb2->y = m3b;
            }
            BAR_SYNC(BCONS, 128);
            BAR_ARRIVE(BEN0 + nb3, 384);   // done with sN/sV buffer
            BAR_ARRIVE(BEQ0 + qb, 384);    // done with sQK[qb] + sSC[qb]

            if (par == 1) {
                // ---- P7: ctx for 8 batches, f32x2 ----
                {
                    int cc = u, h = u >> 4;
                    ull accU[8] = {0,0,0,0,0,0,0,0};
                    #pragma unroll
                    for (int kq = 0; kq < 16; ++kq) {
                        int d = kq * 4;
                        ull w01 = pk2(sWV[(d+0)*128 + cc], sWV[(d+1)*128 + cc]);
                        ull w23 = pk2(sWV[(d+2)*128 + cc], sWV[(d+3)*128 + cc]);
                        #pragma unroll
                        for (int i8 = 0; i8 < 8; ++i8) {
                            ulonglong2 m = *reinterpret_cast<const ulonglong2*>(
                                sM + (i8 >> 2) * 2304 + (i8 & 3) * 576 + h * 72 + d);
                            fma2(accU[i8], w01, m.x);
                            fma2(accU[i8], w23, m.y);
                        }
                    }
                    float bvv = sBV[cc];
                    #pragma unroll
                    for (int i8 = 0; i8 < 8; ++i8) {
                        float2 f = upk(accU[i8]);
                        sCTX[i8 * 128 + cc] = f.x + f.y + bvv;
                    }
                }
                BAR_SYNC(BCONS, 128);

                // ---- P8: out for 8 batches, f32x2 (2-way c split) ----
                {
                    int o = u & 63, cg = u >> 6, c0 = cg * 64;
                    ull accU[8] = {0,0,0,0,0,0,0,0};
                    #pragma unroll
                    for (int kq = 0; kq < 16; ++kq) {
                        int c = c0 + kq * 4;
                        ull w01 = pk2(sWO[(c+0)*64 + o], sWO[(c+1)*64 + o]);
                        ull w23 = pk2(sWO[(c+2)*64 + o], sWO[(c+3)*64 + o]);
                        #pragma unroll
                        for (int i8 = 0; i8 < 8; ++i8) {
                            ulonglong2 x = *reinterpret_cast<const ulonglong2*>(sCTX + i8 * 128 + c);
                            fma2(accU[i8], w01, x.x);
                            fma2(accU[i8], w23, x.y);
                        }
                    }
                    #pragma unroll
                    for (int i8 = 0; i8 < 8; ++i8) {
                        float2 f = upk(accU[i8]);
                        sRED8[cg * 512 + i8 * 64 + o] = f.x + f.y;
                    }
                }
                BAR_SYNC(BCONS, 128);
                #pragma unroll
                for (int p = 0; p < 4; ++p) {
                    int e  = u + p * 128;
                    int i8 = e >> 6, o = e & 63;
                    int bb = (i8 < 4) ? b0_prev : b0;
                    out[(size_t)(bb + (i8 & 3)) * 64 + o] =
                        sRED8[i8 * 64 + o] + sRED8[512 + i8 * 64 + o] + sBO[o];
                }
            } else {
                b0_prev = b0;
            }

            if (++nb3 == 3) nb3 = 0;
        }

        // ---- flush: odd group count leaves sM[0] pending ----
        if (it & 1) {
            {
                int cc = u, h = u >> 4;
                ull accU[4] = {0,0,0,0};
                #pragma unroll
                for (int kq = 0; kq < 16; ++kq) {
                    int d = kq * 4;
                    ull w01 = pk2(sWV[(d+0)*128 + cc], sWV[(d+1)*128 + cc]);
                    ull w23 = pk2(sWV[(d+2)*128 + cc], sWV[(d+3)*128 + cc]);
                    #pragma unroll
                    for (int nb = 0; nb < 4; ++nb) {
                        ulonglong2 m = *reinterpret_cast<const ulonglong2*>(sM + nb * 576 + h * 72 + d);
                        fma2(accU[nb], w01, m.x);
                        fma2(accU[nb], w23, m.y);
                    }
                }
                float bvv = sBV[cc];
                #pragma unroll
                for (int nb = 0; nb < 4; ++nb) {
                    float2 f = upk(accU[nb]);
                    sCTX[nb * 128 + cc] = f.x + f.y + bvv;
                }
            }
            BAR_SYNC(BCONS, 128);
            {
                int o = u & 63, cg = u >> 6, c0 = cg * 64;
                ull accU[4] = {0,0,0,0};
                #pragma unroll
                for (int kq = 0; kq < 16; ++kq) {
                    int c = c0 + kq * 4;
                    ull w01 = pk2(sWO[(c+0)*64 + o], sWO[(c+1)*64 + o]);
                    ull w23 = pk2(sWO[(c+2)*64 + o], sWO[(c+3)*64 + o]);
                    #pragma unroll
                    for (int nb = 0; nb < 4; ++nb) {
                        ulonglong2 x = *reinterpret_cast<const ulonglong2*>(sCTX + nb * 128 + c);
                        fma2(accU[nb], w01, x.x);
                        fma2(accU[nb], w23, x.y);
                    }
                }
                #pragma unroll
                for (int nb = 0; nb < 4; ++nb) {
                    float2 f = upk(accU[nb]);
                    sRED8[cg * 512 + nb * 64 + o] = f.x + f.y;
                }
            }
            BAR_SYNC(BCONS, 128);
            #pragma unroll
            for (int p = 0; p < 2; ++p) {
                int e  = u + p * 128;
                int nb = e >> 6, o = e & 63;
                out[(size_t)(b0_prev + nb) * 64 + o] =
                    sRED8[nb * 64 + o] + sRED8[512 + nb * 64 + o] + sBO[o];
            }
        }
    }
}

extern "C" void kernel_launch(void* const* d_in, const int* in_sizes, int n_in,
                              void* d_out, int out_size)
{
    const float* node_embed = (const float*)d_in[0];
    const int*   start_idx  = (const int*)d_in[1];
    const int*   end_idx    = (const int*)d_in[2];
    /* d_in[3] seg_ids unused (structural) */
    const int*   pad_idx    = (const int*)d_in[4];
    const float* Wq         = (const float*)d_in[5];
    const float* bq         = (const float*)d_in[6];
    const float* Wk         = (const float*)d_in[7];
    /* d_in[8] bk unused (cancels in softmax) */
    const float* Wv         = (const float*)d_in[9];
    const float* bv         = (const float*)d_in[10];
    const float* Wo         = (const float*)d_in[11];
    const float* bo         = (const float*)d_in[12];
    float* out = (float*)d_out;

    int B = out_size / 64;

    cudaFuncSetAttribute(mha_state_encoder_kernel,
                         cudaFuncAttributeMaxDynamicSharedMemorySize, SMEM_BYTES);
    mha_state_encoder_kernel<<<GRID, NT, SMEM_BYTES>>>(
        node_embed, start_idx, end_idx, pad_idx,
        Wq, bq, Wk, Wv, bv, Wo, bo, out, B);
}

// round 15
// speedup vs baseline: 1.1055x; 1.1055x over previous
#include <cuda_runtime.h>
#include <cstdint>
#include <math.h>

// Round 14: R12 base + (producer) agg merged into commit phase (one less
// barrier, overlapped) + (consumer) sQK per-nb stride 576->580 to remove the
// 2-way bank conflict on P5 qk loads.

#define NT 384
#define GRID 148

typedef unsigned long long ull;

// shared memory float offsets
#define OFF_WKT   0        // [128][65]
#define OFF_WV    8320     // [64][128]
#define OFF_WO    16512    // [128][64]
#define OFF_BQ    24704
#define OFF_BV    24832
#define OFF_BO    24960
#define OFF_N     25024    // [3][4][20][68] = 16320
#define OFF_V     41344    // [3][4][20] = 240
#define OFF_QK    41584    // [2][4*580] = 4640  (nb stride 580: bank-spread)
#define OFF_RAW   46224    // [192][4] = 768
#define OFF_Q     46992    // [128][4] = 512
#define OFF_PART  47504    // [4][128][2] ull = 2048 floats
#define OFF_SC    49552    // [4][8][28] = 896
#define OFF_M     50448    // [2][4][8][72] = 4608 (parity-buffered)
#define OFF_CTX   55056    // [8][128] = 1024
#define OFF_RED8  56080    // [2][8][64] = 1024
#define SMEM_FLOATS 57104
#define SMEM_BYTES  (SMEM_FLOATS * 4)   // 228416 B (cap 232448)

#define QK_NB 580          // per-nb stride in sQK
#define QK_QB 2320         // per-qb stride in sQK

// named barrier ids
#define BFULL0 1
#define BEQ0   3
#define BEN0   5
#define BPROD  8
#define BCONS  9

#define BAR_SYNC(id, cnt)   asm volatile("bar.sync %0, %1;"   :: "r"(id), "r"(cnt) : "memory")
#define BAR_ARRIVE(id, cnt) asm volatile("bar.arrive %0, %1;" :: "r"(id), "r"(cnt) : "memory")
#define CP_COMMIT()         asm volatile("cp.async.commit_group;" ::: "memory")
#define CP_WAIT1()          asm volatile("cp.async.wait_group 1;" ::: "memory")

__device__ __forceinline__ ull pk1(float a) {
    ull r; asm("mov.b64 %0, {%1,%1};" : "=l"(r) : "f"(a)); return r;
}
__device__ __forceinline__ ull pk2(float a, float b) {
    ull r; asm("mov.b64 %0, {%1,%2};" : "=l"(r) : "f"(a), "f"(b)); return r;
}
__device__ __forceinline__ void fma2(ull& d, ull a, ull b) {
    asm("fma.rn.f32x2 %0, %1, %2, %0;" : "+l"(d) : "l"(a), "l"(b));
}
__device__ __forceinline__ ull add2(ull a, ull b) {
    ull r; asm("add.rn.f32x2 %0, %1, %2;" : "=l"(r) : "l"(a), "l"(b)); return r;
}
__device__ __forceinline__ ull mul2(ull a, ull b) {
    ull r; asm("mul.rn.f32x2 %0, %1, %2;" : "=l"(r) : "l"(a), "l"(b)); return r;
}
__device__ __forceinline__ float2 upk(ull a) {
    float2 f; asm("mov.b64 {%0,%1}, %2;" : "=f"(f.x), "=f"(f.y) : "l"(a)); return f;
}

__device__ __forceinline__ void issue_node_cp(unsigned int sbase, const float* ne,
                                              int b0, int nbuf, int t) {
    const float4* src = reinterpret_cast<const float4*>(ne) + (size_t)b0 * 320;
    #pragma unroll
    for (int kk = 0; kk < 5; ++kk) {
        int g   = t + kk * 256;
        int nb  = g / 320;
        int rem = g - nb * 320;
        unsigned int dstf = (unsigned int)(OFF_N + nbuf * 5440 + nb * 1360 +
                                           ((rem >> 4) * 17 + (rem & 15)) * 4);
        asm volatile("cp.async.ca.shared.global [%0], [%1], 16;"
                     :: "r"(sbase + dstf * 4), "l"(src + g) : "memory");
    }
}

__global__ void __launch_bounds__(NT, 1)
mha_state_encoder_kernel(const float* __restrict__ node_embed,
                         const int*   __restrict__ start_idx,
                         const int*   __restrict__ end_idx,
                         const int*   __restrict__ pad_idx,
                         const float* __restrict__ Wq, const float* __restrict__ bq,
                         const float* __restrict__ Wk,
                         const float* __restrict__ Wv, const float* __restrict__ bv,
                         const float* __restrict__ Wo, const float* __restrict__ bo,
                         float* __restrict__ out, int B)
{
    extern __shared__ float sm[];
    float* sWKT = sm + OFF_WKT;
    float* sWV  = sm + OFF_WV;
    float* sWO  = sm + OFF_WO;
    float* sBQ  = sm + OFF_BQ;
    float* sBV  = sm + OFF_BV;
    float* sBO  = sm + OFF_BO;
    float* sN   = sm + OFF_N;
    float* sV   = sm + OFF_V;
    float* sQK  = sm + OFF_QK;
    float* sRAW = sm + OFF_RAW;
    float* sSC  = sm + OFF_SC;
    float* sM   = sm + OFF_M;
    float* sCTX = sm + OFF_CTX;
    float* sRED8= sm + OFF_RED8;
    ull*   sQ2  = reinterpret_cast<ull*>(sm + OFF_Q);
    ull*   sPT  = reinterpret_cast<ull*>(sm + OFF_PART);

    unsigned int sbase;
    asm("{ .reg .u64 tt; cvta.to.shared.u64 tt, %1; cvt.u32.u64 %0, tt; }"
        : "=r"(sbase) : "l"(sm));

    const int t  = threadIdx.x;
    const int Qn = B >> 2;
    const int q0 = blockIdx.x;

    // ---- stage weights (whole CTA) ----
    for (int i = t; i < 8192; i += NT) {
        int d = i >> 7, c = i & 127;
        sWKT[c * 65 + d] = Wk[i];
    }
    for (int i = t; i < 2048; i += NT) {
        reinterpret_cast<float4*>(sWV)[i] = reinterpret_cast<const float4*>(Wv)[i];
        reinterpret_cast<float4*>(sWO)[i] = reinterpret_cast<const float4*>(Wo)[i];
    }
    if (t < 128) { sBQ[t] = bq[t]; sBV[t] = bv[t]; }
    if (t < 64)  sBO[t] = bo[t];
    __syncthreads();

    if (t < 256) {
        // ======================= PRODUCER (256 threads) =======================
        const int cl = t & 63;
        const int rg = t >> 6;
        float wq[96];
        {
            const float* src = Wq + (size_t)(rg * 48) * 128 + cl;
            #pragma unroll
            for (int i = 0; i < 24; ++i) {
                wq[4*i+0] = src[(size_t)(2*i)   * 128];
                wq[4*i+1] = src[(size_t)(2*i)   * 128 + 64];
                wq[4*i+2] = src[(size_t)(2*i+1) * 128];
                wq[4*i+3] = src[(size_t)(2*i+1) * 128 + 64];
            }
        }
        const int gg  = t - 128;
        const int gnb = gg & 3;
        const int gwh = (gg >> 2) & 1;
        const int gdq = gg >> 3;

        float4 pfG = make_float4(0.f, 0.f, 0.f, 0.f);
        int pfP = 0, gi_next = 0;

        if (q0 < Qn)        issue_node_cp(sbase, node_embed, q0 * 4, 0, t);
        CP_COMMIT();
        if (q0 + GRID < Qn) issue_node_cp(sbase, node_embed, (q0 + GRID) * 4, 1, t);
        CP_COMMIT();
        if (q0 < Qn) {
            if (t >= 128) {
                int gi = gwh ? end_idx[q0 * 4 + gnb] : start_idx[q0 * 4 + gnb];
                pfG = *reinterpret_cast<const float4*>(node_embed + (size_t)gi * 64 + gdq * 4);
                int qn = q0 + GRID;
                if (qn < Qn) gi_next = gwh ? end_idx[qn * 4 + gnb] : start_idx[qn * 4 + gnb];
            }
            if (t < 80) pfP = pad_idx[q0 * 80 + t];
        }

        int it = 0, nb3 = 0;
        for (int q = q0; q < Qn; q += GRID, ++it) {
            const int qb = it & 1;

            CP_WAIT1();   // this group's node tile landed

            // ---- commit phase: gathers (t>=128) + valid (t<80) + agg (t<64) ----
            if (t >= 128) {
                int r0 = 64 + gwh * 64 + gdq * 4;
                sRAW[(r0 + 0) * 4 + gnb] = pfG.x;
                sRAW[(r0 + 1) * 4 + gnb] = pfG.y;
                sRAW[(r0 + 2) * 4 + gnb] = pfG.z;
                sRAW[(r0 + 3) * 4 + gnb] = pfG.w;
                // prefetch gathers for next group
                if (q + GRID < Qn) {
                    pfG = *reinterpret_cast<const float4*>(node_embed + (size_t)gi_next * 64 + gdq * 4);
                    int qn2 = q + 2 * GRID;
                    if (qn2 < Qn) gi_next = gwh ? end_idx[qn2 * 4 + gnb] : start_idx[qn2 * 4 + gnb];
                }
            } else {
                if (t < 80) {
                    sV[nb3 * 80 + t] = (pfP >= 0) ? 1.0f : 0.0f;
                    if (q + GRID < Qn) pfP = pad_idx[(q + GRID) * 80 + t];
                }
                if (t < 64) {
                    // P2: agg (column sums, f32x2) — rows 0..63 of sRAW (disjoint
                    // from gather rows 64..191)
                    int nb = t >> 4, dq = t & 15;
                    const ulonglong2* col = reinterpret_cast<const ulonglong2*>(sN + nb3 * 5440 + nb * 1360) + dq;
                    ull s01 = 0, s23 = 0;
                    #pragma unroll
                    for (int j = 0; j < 20; ++j) {
                        ulonglong2 x = col[j * 17];
                        s01 = add2(s01, x.x);
                        s23 = add2(s23, x.y);
                    }
                    float2 a01 = upk(s01), a23 = upk(s23);
                    int r0 = dq * 4;
                    sRAW[(r0 + 0) * 4 + nb] = a01.x;
                    sRAW[(r0 + 1) * 4 + nb] = a01.y;
                    sRAW[(r0 + 2) * 4 + nb] = a23.x;
                    sRAW[(r0 + 3) * 4 + nb] = a23.y;
                }
            }
            BAR_SYNC(BPROD, 256);

            // ---- P3a: q partials ----
            {
                const ulonglong2* pR = reinterpret_cast<const ulonglong2*>(sRAW) + rg * 48;
                ull a0 = 0, a1 = 0, b0u = 0, b1u = 0;
                #pragma unroll
                for (int i = 0; i < 24; ++i) {
                    ulonglong2 x = pR[2 * i];
                    ulonglong2 y = pR[2 * i + 1];
                    ull w0 = pk1(wq[4*i+0]), w1 = pk1(wq[4*i+1]);
                    ull w2 = pk1(wq[4*i+2]), w3 = pk1(wq[4*i+3]);
                    fma2(a0,  w0, x.x); fma2(a1,  w0, x.y);
                    fma2(b0u, w1, x.x); fma2(b1u, w1, x.y);
                    fma2(a0,  w2, y.x); fma2(a1,  w2, y.y);
                    fma2(b0u, w3, y.x); fma2(b1u, w3, y.y);
                }
                ull* dA = sPT + rg * 256 + cl * 2;
                dA[0] = a0; dA[1] = a1;
                ull* dB = sPT + rg * 256 + (cl + 64) * 2;
                dB[0] = b0u; dB[1] = b1u;
            }
            BAR_SYNC(BPROD, 256);

            // ---- P3b: combine + bias + 0.25 ----
            {
                int c = t >> 1, pp = t & 1;
                int o = c * 2 + pp;
                ull v = add2(add2(sPT[o], sPT[256 + o]),
                             add2(sPT[512 + o], sPT[768 + o]));
                v = add2(v, pk1(sBQ[c]));
                v = mul2(v, pk1(0.25f));
                sQ2[c * 2 + pp] = v;
            }
            BAR_SYNC(BPROD, 256);

            // ---- P4: qk -> sQK[qb] (nb stride QK_NB) ----
            if (it >= 2) BAR_SYNC(BEQ0 + qb, 384);
            #pragma unroll
            for (int p = 0; p < 2; ++p) {
                int v2 = t + p * 256;
                int h = v2 >> 6, d = v2 & 63;
                const float* wkb = sWKT + h * 16 * 65 + d;
                const ulonglong2* q2 = reinterpret_cast<const ulonglong2*>(sQ2) + h * 16;
                ull a01 = 0, a23 = 0;
                #pragma unroll
                for (int i = 0; i < 16; ++i) {
                    ull wp = pk1(wkb[i * 65]);
                    ulonglong2 qv = q2[i];
                    fma2(a01, wp, qv.x);
                    fma2(a23, wp, qv.y);
                }
                float2 f01 = upk(a01), f23 = upk(a23);
                float* dst = sQK + qb * QK_QB + h * 72 + d;
                dst[0 * QK_NB] = f01.x; dst[1 * QK_NB] = f01.y;
                dst[2 * QK_NB] = f23.x; dst[3 * QK_NB] = f23.y;
            }
            BAR_ARRIVE(BFULL0 + qb, 384);

            // ---- issue node cp.async for group q+2*GRID ----
            {
                int nb3p2 = nb3 + 2; if (nb3p2 >= 3) nb3p2 -= 3;
                if (q + 2 * GRID < Qn) {
                    if (it >= 1) BAR_SYNC(BEN0 + nb3p2, 384);
                    issue_node_cp(sbase, node_embed, (q + 2 * GRID) * 4, nb3p2, t);
                }
                CP_COMMIT();
            }
            if (++nb3 == 3) nb3 = 0;
        }
    } else {
        // ======================= CONSUMER (128 threads) =======================
        const int u = t - 256;
        int it = 0, nb3 = 0;
        int b0_prev = 0;
        for (int q = q0; q < Qn; q += GRID, ++it) {
            const int b0 = q * 4;
            const int qb  = it & 1;
            const int par = it & 1;
            const float* nbase = sN + nb3 * 5440;
            const float* vbase = sV + nb3 * 80;
            const float* qkB   = sQK + qb * QK_QB;
            float* sMp = sM + par * 2304;

            BAR_SYNC(BFULL0 + qb, 384);

            // ---- P5: 80 tasks (nb,j) x 8 heads, f32x2 ----
            if (u < 80) {
                int nb = u / 20, j = u - nb * 20;
                const ulonglong2* n2 = reinterpret_cast<const ulonglong2*>(nbase + nb * 1360 + j * 68);
                const float* qkb = qkB + nb * QK_NB;
                ull acc0 = 0, acc1 = 0, acc2 = 0, acc3 = 0;
                ull acc4 = 0, acc5 = 0, acc6 = 0, acc7 = 0;
                ull rs = 0;
                #pragma unroll
                for (int k = 0; k < 16; ++k) {
                    ulonglong2 x = n2[k];
                    rs = add2(rs, add2(x.x, x.y));
                    ulonglong2 q0v = *reinterpret_cast<const ulonglong2*>(qkb + 0 * 72 + k * 4);
                    ulonglong2 q1v = *reinterpret_cast<const ulonglong2*>(qkb + 1 * 72 + k * 4);
                    ulonglong2 q2v = *reinterpret_cast<const ulonglong2*>(qkb + 2 * 72 + k * 4);
                    ulonglong2 q3v = *reinterpret_cast<const ulonglong2*>(qkb + 3 * 72 + k * 4);
                    ulonglong2 q4v = *reinterpret_cast<const ulonglong2*>(qkb + 4 * 72 + k * 4);
                    ulonglong2 q5v = *reinterpret_cast<const ulonglong2*>(qkb + 5 * 72 + k * 4);
                    ulonglong2 q6v = *reinterpret_cast<const ulonglong2*>(qkb + 6 * 72 + k * 4);
                    ulonglong2 q7v = *reinterpret_cast<const ulonglong2*>(qkb + 7 * 72 + k * 4);
                    fma2(acc0, q0v.x, x.x); fma2(acc0, q0v.y, x.y);
                    fma2(acc1, q1v.x, x.x); fma2(acc1, q1v.y, x.y);
                    fma2(acc2, q2v.x, x.x); fma2(acc2, q2v.y, x.y);
                    fma2(acc3, q3v.x, x.x); fma2(acc3, q3v.y, x.y);
                    fma2(acc4, q4v.x, x.x); fma2(acc4, q4v.y, x.y);
                    fma2(acc5, q5v.x, x.x); fma2(acc5, q5v.y, x.y);
                    fma2(acc6, q6v.x, x.x); fma2(acc6, q6v.y, x.y);
                    fma2(acc7, q7v.x, x.x); fma2(acc7, q7v.y, x.y);
                }
                float2 rf = upk(rs);
                float rsum = rf.x + rf.y;
                float msk = (vbase[nb * 20 + j] == 0.f || rsum == 0.f) ? -1e9f : 0.f;
                float* dst = sSC + nb * 224 + j;
                float2 f;
                f = upk(acc0); dst[0 * 28] = f.x + f.y + msk;
                f = upk(acc1); dst[1 * 28] = f.x + f.y + msk;
                f = upk(acc2); dst[2 * 28] = f.x + f.y + msk;
                f = upk(acc3); dst[3 * 28] = f.x + f.y + msk;
                f = upk(acc4); dst[4 * 28] = f.x + f.y + msk;
                f = upk(acc5); dst[5 * 28] = f.x + f.y + msk;
                f = upk(acc6); dst[6 * 28] = f.x + f.y + msk;
                f = upk(acc7); dst[7 * 28] = f.x + f.y + msk;
            }
            BAR_SYNC(BCONS, 128);
            BAR_ARRIVE(BEQ0 + qb, 384);

            // ---- softmax: 32 rows x 4 lanes ----
            {
                int row = u >> 2, j0 = u & 3;
                int nb = row >> 3, h = row & 7;
                float* base = sSC + nb * 224 + h * 28;
                const float* vd = vbase + nb * 20;
                float x0 = base[j0], x1 = base[j0+4], x2 = base[j0+8], x3 = base[j0+12], x4 = base[j0+16];
                float mx = fmaxf(fmaxf(fmaxf(x0, x1), fmaxf(x2, x3)), x4);
                mx = fmaxf(mx, __shfl_xor_sync(0xffffffffu, mx, 1));
                mx = fmaxf(mx, __shfl_xor_sync(0xffffffffu, mx, 2));
                float e0 = __expf(x0 - mx), e1 = __expf(x1 - mx), e2 = __expf(x2 - mx);
                float e3 = __expf(x3 - mx), e4 = __expf(x4 - mx);
                float s = ((e0 + e1) + (e2 + e3)) + e4;
                s += __shfl_xor_sync(0xffffffffu, s, 1);
                s += __shfl_xor_sync(0xffffffffu, s, 2);
                float inv = __fdividef(1.f, s);
                base[j0]      = e0 * inv * vd[j0];
                base[j0 + 4]  = e1 * inv * vd[j0 + 4];
                base[j0 + 8]  = e2 * inv * vd[j0 + 8];
                base[j0 + 12] = e3 * inv * vd[j0 + 12];
                base[j0 + 16] = e4 * inv * vd[j0 + 16];
            }
            BAR_SYNC(BCONS, 128);

            // ---- P6: m (4 heads/thread, f32x2) -> sM[par] ----
            {
                int nb = u >> 5, dq = (u >> 1) & 15, hg = u & 1;
                const ulonglong2* n2 = reinterpret_cast<const ulonglong2*>(nbase + nb * 1360) + dq;
                const float* a0 = sSC + nb * 224 + (hg * 4 + 0) * 28;
                const float* a1 = sSC + nb * 224 + (hg * 4 + 1) * 28;
                const float* a2 = sSC + nb * 224 + (hg * 4 + 2) * 28;
                const float* a3 = sSC + nb * 224 + (hg * 4 + 3) * 28;
                ull m0a = 0, m0b = 0, m1a = 0, m1b = 0;
                ull m2a = 0, m2b = 0, m3a = 0, m3b = 0;
                #pragma unroll
                for (int jq = 0; jq < 5; ++jq) {
                    float4 w0 = *reinterpret_cast<const float4*>(a0 + jq * 4);
                    float4 w1 = *reinterpret_cast<const float4*>(a1 + jq * 4);
                    float4 w2 = *reinterpret_cast<const float4*>(a2 + jq * 4);
                    float4 w3 = *reinterpret_cast<const float4*>(a3 + jq * 4);
                    #pragma unroll
                    for (int jj = 0; jj < 4; ++jj) {
                        ulonglong2 x = n2[(jq * 4 + jj) * 17];
                        float c0 = jj == 0 ? w0.x : jj == 1 ? w0.y : jj == 2 ? w0.z : w0.w;
                        float c1 = jj == 0 ? w1.x : jj == 1 ? w1.y : jj == 2 ? w1.z : w1.w;
                        float c2 = jj == 0 ? w2.x : jj == 1 ? w2.y : jj == 2 ? w2.z : w2.w;
                        float c3 = jj == 0 ? w3.x : jj == 1 ? w3.y : jj == 2 ? w3.z : w3.w;
                        ull p0 = pk1(c0), p1 = pk1(c1), p2 = pk1(c2), p3 = pk1(c3);
                        fma2(m0a, p0, x.x); fma2(m0b, p0, x.y);
                        fma2(m1a, p1, x.x); fma2(m1b, p1, x.y);
                        fma2(m2a, p2, x.x); fma2(m2b, p2, x.y);
                        fma2(m3a, p3, x.x); fma2(m3b, p3, x.y);
                    }
                }
                float* mb = sMp + nb * 576 + (hg * 4) * 72 + dq * 4;
                ulonglong2* mb2;
                mb2 = reinterpret_cast<ulonglong2*>(mb + 0 * 72); mb2->x = m0a; mb2->y = m0b;
                mb2 = reinterpret_cast<ulonglong2*>(mb + 1 * 72); mb2->x = m1a; mb2->y = m1b;
                mb2 = reinterpret_cast<ulonglong2*>(mb + 2 * 72); mb2->x = m2a; mb2->y = m2b;
                mb2 = reinterpret_cast<ulonglong2*>(mb + 3 * 72); mb2->x = m3a; mb2->y = m3b;
            }
            BAR_SYNC(BCONS, 128);
            BAR_ARRIVE(BEN0 + nb3, 384);

            if (par == 1) {
                // ---- P7: ctx for 8 batches, f32x2 ----
                {
                    int cc = u, h = u >> 4;
                    ull accU[8] = {0,0,0,0,0,0,0,0};
                    #pragma unroll
                    for (int kq = 0; kq < 16; ++kq) {
                        int d = kq * 4;
                        ull w01 = pk2(sWV[(d+0)*128 + cc], sWV[(d+1)*128 + cc]);
                        ull w23 = pk2(sWV[(d+2)*128 + cc], sWV[(d+3)*128 + cc]);
                        #pragma unroll
                        for (int i8 = 0; i8 < 8; ++i8) {
                            ulonglong2 m = *reinterpret_cast<const ulonglong2*>(
                                sM + (i8 >> 2) * 2304 + (i8 & 3) * 576 + h * 72 + d);
                            fma2(accU[i8], w01, m.x);
                            fma2(accU[i8], w23, m.y);
                        }
                    }
                    float bvv = sBV[cc];
                    #pragma unroll
                    for (int i8 = 0; i8 < 8; ++i8) {
                        float2 f = upk(accU[i8]);
                        sCTX[i8 * 128 + cc] = f.x + f.y + bvv;
                    }
                }
                BAR_SYNC(BCONS, 128);

                // ---- P8: out for 8 batches, f32x2 (2-way c split) ----
                {
                    int o = u & 63, cg = u >> 6, c0 = cg * 64;
                    ull accU[8] = {0,0,0,0,0,0,0,0};
                    #pragma unroll
                    for (int kq = 0; kq < 16; ++kq) {
                        int c = c0 + kq * 4;
                        ull w01 = pk2(sWO[(c+0)*64 + o], sWO[(c+1)*64 + o]);
                        ull w23 = pk2(sWO[(c+2)*64 + o], sWO[(c+3)*64 + o]);
                        #pragma unroll
                        for (int i8 = 0; i8 < 8; ++i8) {
                            ulonglong2 x = *reinterpret_cast<const ulonglong2*>(sCTX + i8 * 128 + c);
                            fma2(accU[i8], w01, x.x);
                            fma2(accU[i8], w23, x.y);
                        }
                    }
                    #pragma unroll
                    for (int i8 = 0; i8 < 8; ++i8) {
                        float2 f = upk(accU[i8]);
                        sRED8[cg * 512 + i8 * 64 + o] = f.x + f.y;
                    }
                }
                BAR_SYNC(BCONS, 128);
                #pragma unroll
                for (int p = 0; p < 4; ++p) {
                    int e  = u + p * 128;
                    int i8 = e >> 6, o = e & 63;
                    int bb = (i8 < 4) ? b0_prev : b0;
                    out[(size_t)(bb + (i8 & 3)) * 64 + o] =
                        sRED8[i8 * 64 + o] + sRED8[512 + i8 * 64 + o] + sBO[o];
                }
            } else {
                b0_prev = b0;
            }

            if (++nb3 == 3) nb3 = 0;
        }

        // ---- flush: odd group count leaves sM[0] pending ----
        if (it & 1) {
            {
                int cc = u, h = u >> 4;
                ull accU[4] = {0,0,0,0};
                #pragma unroll
                for (int kq = 0; kq < 16; ++kq) {
                    int d = kq * 4;
                    ull w01 = pk2(sWV[(d+0)*128 + cc], sWV[(d+1)*128 + cc]);
                    ull w23 = pk2(sWV[(d+2)*128 + cc], sWV[(d+3)*128 + cc]);
                    #pragma unroll
                    for (int nb = 0; nb < 4; ++nb) {
                        ulonglong2 m = *reinterpret_cast<const ulonglong2*>(sM + nb * 576 + h * 72 + d);
                        fma2(accU[nb], w01, m.x);
                        fma2(accU[nb], w23, m.y);
                    }
                }
                float bvv = sBV[cc];
                #pragma unroll
                for (int nb = 0; nb < 4; ++nb) {
                    float2 f = upk(accU[nb]);
                    sCTX[nb * 128 + cc] = f.x + f.y + bvv;
                }
            }
            BAR_SYNC(BCONS, 128);
            {
                int o = u & 63, cg = u >> 6, c0 = cg * 64;
                ull accU[4] = {0,0,0,0};
                #pragma unroll
                for (int kq = 0; kq < 16; ++kq) {
                    int c = c0 + kq * 4;
                    ull w01 = pk2(sWO[(c+0)*64 + o], sWO[(c+1)*64 + o]);
                    ull w23 = pk2(sWO[(c+2)*64 + o], sWO[(c+3)*64 + o]);
                    #pragma unroll
                    for (int nb = 0; nb < 4; ++nb) {
                        ulonglong2 x = *reinterpret_cast<const ulonglong2*>(sCTX + nb * 128 + c);
                        fma2(accU[nb], w01, x.x);
                        fma2(accU[nb], w23, x.y);
                    }
                }
                #pragma unroll
                for (int nb = 0; nb < 4; ++nb) {
                    float2 f = upk(accU[nb]);
                    sRED8[cg * 512 + nb * 64 + o] = f.x + f.y;
                }
            }
            BAR_SYNC(BCONS, 128);
            #pragma unroll
            for (int p = 0; p < 2; ++p) {
                int e  = u + p * 128;
                int nb = e >> 6, o = e & 63;
                out[(size_t)(b0_prev + nb) * 64 + o] =
                    sRED8[nb * 64 + o] + sRED8[512 + nb * 64 + o] + sBO[o];
            }
        }
    }
}

extern "C" void kernel_launch(void* const* d_in, const int* in_sizes, int n_in,
                              void* d_out, int out_size)
{
    const float* node_embed = (const float*)d_in[0];
    const int*   start_idx  = (const int*)d_in[1];
    const int*   end_idx    = (const int*)d_in[2];
    /* d_in[3] seg_ids unused (structural) */
    const int*   pad_idx    = (const int*)d_in[4];
    const float* Wq         = (const float*)d_in[5];
    const float* bq         = (const float*)d_in[6];
    const float* Wk         = (const float*)d_in[7];
    /* d_in[8] bk unused (cancels in softmax) */
    const float* Wv         = (const float*)d_in[9];
    const float* bv         = (const float*)d_in[10];
    const float* Wo         = (const float*)d_in[11];
    const float* bo         = (const float*)d_in[12];
    float* out = (float*)d_out;

    int B = out_size / 64;

    cudaFuncSetAttribute(mha_state_encoder_kernel,
                         cudaFuncAttributeMaxDynamicSharedMemorySize, SMEM_BYTES);
    mha_state_encoder_kernel<<<GRID, NT, SMEM_BYTES>>>(
        node_embed, start_idx, end_idx, pad_idx,
        Wq, bq, Wk, Wv, bv, Wo, bo, out, B);
}